// round 9
// baseline (speedup 1.0000x reference)
#include <cuda_runtime.h>

#define NBATCH   131072
#define GDIM     9
#define CELLS    81
#define NWAVE    3
#define NB       3              // batch items per iteration
#define K_ITERS  16             // batch-triples per block -> 48 batches/block
#define NTHREADS 256
#define ACTIVE   (NB * CELLS)   // 243 (= CELLS*NWAVE)
#define LUT_ENTRIES (CELLS * 10)   // 810

__global__ __launch_bounds__(NTHREADS)
void photonic_fused_kernel(const int*   __restrict__ grid,    // [B,81]
                           const float* __restrict__ nidx,    // [9,9]
                           const float* __restrict__ absorb,  // [9,9,3]
                           const float* __restrict__ ts_ptr,  // scalar
                           float*       __restrict__ feats,   // [B,81,4]
                           float*       __restrict__ resp)    // [B,81,3]
{
    __shared__ float  s_r[LUT_ENTRIES * 3];   // r0,r1,r2 per (cell,g)
    __shared__ float2 s_mv[LUT_ENTRIES];      // (mean, var) per (cell,g), 8B aligned

    const int t = threadIdx.x;

    // ---- Phase 1: build LUT (810 entries over 256 threads) ----
    // EXACT f32 op sequence of the passing kernels => bit-identical outputs.
    {
        const float ts = __ldg(ts_ptr);
        for (int e = t; e < LUT_ENTRIES; e += NTHREADS) {
            const int cell = e / 10;
            const int g    = e - cell * 10;

            const float n = __ldg(&nidx[cell]);

            const float heights = 1e-4f + ts * (float)g;
            const float path    = heights * n;

            const float d    = (1.0f - n) / (1.0f + n);
            const float frac = 1.0f - d * d;

            const float two_pi_path = 6.283185307179586f * path;

            const float a0 = fabsf(__ldg(&absorb[cell * 3 + 0]));
            const float a1 = fabsf(__ldg(&absorb[cell * 3 + 1]));
            const float a2 = fabsf(__ldg(&absorb[cell * 3 + 2]));

            const float t0 = expf(-a0 * path);
            const float t1 = expf(-a1 * path);
            const float t2 = expf(-a2 * path);

            const float i0 = 0.5f * (1.0f + cosf(two_pi_path / 6.5e-07f));
            const float i1 = 0.5f * (1.0f + cosf(two_pi_path / 5.5e-07f));
            const float i2 = 0.5f * (1.0f + cosf(two_pi_path / 4.5e-07f));

            const float r0 = frac * t0 * i0;
            const float r1 = frac * t1 * i1;
            const float r2 = frac * t2 * i2;

            const float m  = (r0 + r1 + r2) / 3.0f;
            const float e0 = r0 - m, e1 = r1 - m, e2 = r2 - m;
            const float var = (e0 * e0 + e1 * e1 + e2 * e2) * 0.5f;

            s_r[e * 3 + 0] = r0;
            s_r[e * 3 + 1] = r1;
            s_r[e * 3 + 2] = r2;
            s_mv[e] = make_float2(m, var);
        }
    }
    __syncthreads();   // only barrier — LUT is read-only below

    if (t >= ACTIVE) return;

    // resp mapping: thread t -> (cell_r = t/3, w = t%3); writes resp[b*243 + t]
    const int cell_r = t / 3;
    const int w      = t - cell_r * 3;

    // feats mapping: thread t -> (local_b = t/81, cell = t%81)
    const int local_b = t / CELLS;
    const int cell    = t - local_b * CELLS;
    const int ci      = cell / GDIM;
    const int cj      = cell - ci * GDIM;
    const bool has_r  = (cj < GDIM - 1);
    const bool has_d  = (ci < GDIM - 1);
    const int  off_r  = has_r ? 1 : 0;
    const int  off_d  = has_d ? GDIM : 0;

    const int base0 = blockIdx.x * (NB * K_ITERS);

    if (base0 + NB * K_ITERS <= NBATCH) {
        // ---- Fast path: full 48-batch block, no guards, no break ----
        #pragma unroll 4
        for (int k = 0; k < K_ITERS; k++) {
            const int base_batch = base0 + k * NB;

            // resp: 3 unit-stride coalesced streaming stores
            #pragma unroll
            for (int lb = 0; lb < NB; lb++) {
                const long b = (long)(base_batch + lb);
                const int g = __ldg(&grid[b * CELLS + cell_r]);
                __stcs(&resp[b * (CELLS * NWAVE) + t],
                       s_r[(cell_r * 10 + g) * 3 + w]);
            }

            // feats: float4 streaming store
            {
                const long b = (long)(base_batch + local_b);
                const int* grow = grid + b * CELLS;
                const int g  = __ldg(&grow[cell]);
                const int gr = __ldg(&grow[cell + off_r]);  // L1 hit
                const int gd = __ldg(&grow[cell + off_d]);  // L1 hit

                const float2 mv = s_mv[cell * 10 + g];
                const float  mr = s_mv[(cell + off_r) * 10 + gr].x;
                const float  md = s_mv[(cell + off_d) * 10 + gd].x;
                const float  gx = has_r ? (mr - mv.x) : 0.0f;
                const float  gy = has_d ? (md - mv.x) : 0.0f;

                __stcs(reinterpret_cast<float4*>(feats) + b * CELLS + cell,
                       make_float4(mv.x, mv.y, gx, gy));
            }
        }
    } else {
        // ---- Tail path: guarded (last block only) ----
        for (int k = 0; k < K_ITERS; k++) {
            const int base_batch = base0 + k * NB;
            if (base_batch >= NBATCH) break;

            #pragma unroll
            for (int lb = 0; lb < NB; lb++) {
                const long b = (long)(base_batch + lb);
                if (b < NBATCH) {
                    const int g = __ldg(&grid[b * CELLS + cell_r]);
                    __stcs(&resp[b * (CELLS * NWAVE) + t],
                           s_r[(cell_r * 10 + g) * 3 + w]);
                }
            }

            const long b = (long)(base_batch + local_b);
            if (b < NBATCH) {
                const int* grow = grid + b * CELLS;
                const int g  = __ldg(&grow[cell]);
                const int gr = __ldg(&grow[cell + off_r]);
                const int gd = __ldg(&grow[cell + off_d]);

                const float2 mv = s_mv[cell * 10 + g];
                const float  mr = s_mv[(cell + off_r) * 10 + gr].x;
                const float  md = s_mv[(cell + off_d) * 10 + gd].x;
                const float  gx = has_r ? (mr - mv.x) : 0.0f;
                const float  gy = has_d ? (md - mv.x) : 0.0f;

                __stcs(reinterpret_cast<float4*>(feats) + b * CELLS + cell,
                       make_float4(mv.x, mv.y, gx, gy));
            }
        }
    }
}

extern "C" void kernel_launch(void* const* d_in, const int* in_sizes, int n_in,
                              void* d_out, int out_size)
{
    const int*   grid_p = (const int*)  d_in[0];   // sudoku_grid [B,9,9] int32
    const float* nidx_p = (const float*)d_in[1];   // refractive_indices [9,9]
    const float* absb_p = (const float*)d_in[2];   // absorption_coeffs [9,9,3]
    const float* ts_p   = (const float*)d_in[3];   // thickness_scale scalar

    float* feats_p = (float*)d_out;                            // [B,9,9,4]
    float* resp_p  = feats_p + (size_t)NBATCH * CELLS * 4;     // [B,9,9,3]

    const int batches_per_block = NB * K_ITERS;                // 48
    const int nblocks = (NBATCH + batches_per_block - 1) / batches_per_block;
    photonic_fused_kernel<<<nblocks, NTHREADS>>>(grid_p, nidx_p, absb_p, ts_p,
                                                 feats_p, resp_p);
}

// round 10
// speedup vs baseline: 1.0592x; 1.0592x over previous
#include <cuda_runtime.h>

#define NBATCH   131072
#define GDIM     9
#define CELLS    81
#define NWAVE    3
#define NB       3              // batch items per iteration (243-thread mapping)
#define K_ITERS  16             // batch-triples per block -> 48 batches/block
#define NTHREADS 256
#define ACTIVE   (NB * CELLS)   // 243
#define LUT_ENTRIES (CELLS * 10)   // 810

__global__ __launch_bounds__(NTHREADS)
void photonic_fused_kernel(const int*   __restrict__ grid,    // [B,81]
                           const float* __restrict__ nidx,    // [9,9]
                           const float* __restrict__ absorb,  // [9,9,3]
                           const float* __restrict__ ts_ptr,  // scalar
                           float*       __restrict__ feats,   // [B,81,4]
                           float*       __restrict__ resp)    // [B,81,3]
{
    __shared__ float  s_r[LUT_ENTRIES * 3];   // r0,r1,r2 per (cell,g)
    __shared__ float2 s_mv[LUT_ENTRIES];      // (mean,var), 8B-aligned -> LDS.64

    const int t = threadIdx.x;

    // ---- Phase 1: build LUT (810 entries over 256 threads) ----
    // EXACT f32 op sequence of the passing kernels => bit-identical outputs.
    {
        const float ts = __ldg(ts_ptr);
        for (int e = t; e < LUT_ENTRIES; e += NTHREADS) {
            const int cell = e / 10;
            const int g    = e - cell * 10;

            const float n = __ldg(&nidx[cell]);

            const float heights = 1e-4f + ts * (float)g;
            const float path    = heights * n;

            const float d    = (1.0f - n) / (1.0f + n);
            const float frac = 1.0f - d * d;

            const float two_pi_path = 6.283185307179586f * path;

            const float a0 = fabsf(__ldg(&absorb[cell * 3 + 0]));
            const float a1 = fabsf(__ldg(&absorb[cell * 3 + 1]));
            const float a2 = fabsf(__ldg(&absorb[cell * 3 + 2]));

            const float t0 = expf(-a0 * path);
            const float t1 = expf(-a1 * path);
            const float t2 = expf(-a2 * path);

            const float i0 = 0.5f * (1.0f + cosf(two_pi_path / 6.5e-07f));
            const float i1 = 0.5f * (1.0f + cosf(two_pi_path / 5.5e-07f));
            const float i2 = 0.5f * (1.0f + cosf(two_pi_path / 4.5e-07f));

            const float r0 = frac * t0 * i0;
            const float r1 = frac * t1 * i1;
            const float r2 = frac * t2 * i2;

            const float m  = (r0 + r1 + r2) / 3.0f;
            const float e0 = r0 - m, e1 = r1 - m, e2 = r2 - m;
            const float var = (e0 * e0 + e1 * e1 + e2 * e2) * 0.5f;

            s_r[e * 3 + 0] = r0;
            s_r[e * 3 + 1] = r1;
            s_r[e * 3 + 2] = r2;
            s_mv[e] = make_float2(m, var);
        }
    }
    __syncthreads();   // only barrier — LUT read-only below

    if (t >= ACTIVE) return;

    const int local_b = t / CELLS;            // 0..2
    const int cell    = t - local_b * CELLS;  // 0..80
    const int ci      = cell / GDIM;
    const int cj      = cell - ci * GDIM;
    const bool has_r  = (cj < GDIM - 1);
    const bool has_d  = (ci < GDIM - 1);
    const int  off_r  = has_r ? 1 : 0;
    const int  off_d  = has_d ? GDIM : 0;

    const int  base0 = blockIdx.x * (NB * K_ITERS);
    const long b0    = (long)base0 + local_b;

    if (base0 + NB * K_ITERS <= NBATCH) {
        // ---- Fast path: guard-free, 1-iteration grid prefetch ----
        const int* gp = grid + b0 * CELLS;
        int g  = __ldg(gp + cell);
        int gr = __ldg(gp + cell + off_r);
        int gd = __ldg(gp + cell + off_d);

        #pragma unroll 1
        for (int k = 0; k < K_ITERS; k++) {
            const long b = b0 + (long)k * NB;
            const int cg = g, cgr = gr, cgd = gd;

            if (k + 1 < K_ITERS) {                     // prefetch next iter
                const int* gn = grid + (b + NB) * CELLS;
                g  = __ldg(gn + cell);
                gr = __ldg(gn + cell + off_r);
                gd = __ldg(gn + cell + off_d);
            }

            const float2 mv = s_mv[cell * 10 + cg];
            const float  mr = s_mv[(cell + off_r) * 10 + cgr].x;
            const float  md = s_mv[(cell + off_d) * 10 + cgd].x;
            const float  gx = has_r ? (mr - mv.x) : 0.0f;
            const float  gy = has_d ? (md - mv.x) : 0.0f;

            __stcs(reinterpret_cast<float4*>(feats) + b * CELLS + cell,
                   make_float4(mv.x, mv.y, gx, gy));

            const float* rr = &s_r[(cell * 10 + cg) * 3];
            const long ro = (b * CELLS + cell) * NWAVE;
            __stcs(&resp[ro + 0], rr[0]);
            __stcs(&resp[ro + 1], rr[1]);
            __stcs(&resp[ro + 2], rr[2]);
        }
    } else {
        // ---- Tail path (last block only): guarded, no prefetch ----
        #pragma unroll 1
        for (int k = 0; k < K_ITERS; k++) {
            const long b = b0 + (long)k * NB;
            if (b >= NBATCH) break;

            const int* gp = grid + b * CELLS;
            const int cg  = __ldg(gp + cell);
            const int cgr = __ldg(gp + cell + off_r);
            const int cgd = __ldg(gp + cell + off_d);

            const float2 mv = s_mv[cell * 10 + cg];
            const float  mr = s_mv[(cell + off_r) * 10 + cgr].x;
            const float  md = s_mv[(cell + off_d) * 10 + cgd].x;
            const float  gx = has_r ? (mr - mv.x) : 0.0f;
            const float  gy = has_d ? (md - mv.x) : 0.0f;

            __stcs(reinterpret_cast<float4*>(feats) + b * CELLS + cell,
                   make_float4(mv.x, mv.y, gx, gy));

            const float* rr = &s_r[(cell * 10 + cg) * 3];
            const long ro = (b * CELLS + cell) * NWAVE;
            __stcs(&resp[ro + 0], rr[0]);
            __stcs(&resp[ro + 1], rr[1]);
            __stcs(&resp[ro + 2], rr[2]);
        }
    }
}

extern "C" void kernel_launch(void* const* d_in, const int* in_sizes, int n_in,
                              void* d_out, int out_size)
{
    const int*   grid_p = (const int*)  d_in[0];   // sudoku_grid [B,9,9] int32
    const float* nidx_p = (const float*)d_in[1];   // refractive_indices [9,9]
    const float* absb_p = (const float*)d_in[2];   // absorption_coeffs [9,9,3]
    const float* ts_p   = (const float*)d_in[3];   // thickness_scale scalar

    float* feats_p = (float*)d_out;                            // [B,9,9,4]
    float* resp_p  = feats_p + (size_t)NBATCH * CELLS * 4;     // [B,9,9,3]

    const int batches_per_block = NB * K_ITERS;                // 48
    const int nblocks = (NBATCH + batches_per_block - 1) / batches_per_block;
    photonic_fused_kernel<<<nblocks, NTHREADS>>>(grid_p, nidx_p, absb_p, ts_p,
                                                 feats_p, resp_p);
}